// round 5
// baseline (speedup 1.0000x reference)
#include <cuda_runtime.h>
#include <cstdint>
#include <math.h>

#define BB 256
#define TT 40
#define DD 100
#define D2 200
#define NNODE 200000
#define NOUT 199999   // N_NODE - 1

// scratch for ma [256][200] (device global: no allocation allowed)
__device__ float g_ma[BB * D2];

// ---------------------------------------------------------------------------
// helpers
// ---------------------------------------------------------------------------
__device__ __forceinline__ float tf32_of(float x) {
    uint32_t u;
    asm("cvt.rna.tf32.f32 %0, %1;" : "=r"(u) : "f"(x));
    return __uint_as_float(u);
}

__device__ __forceinline__ void mma_tf32(float d[4],
                                         uint32_t a0, uint32_t a1, uint32_t a2, uint32_t a3,
                                         uint32_t b0, uint32_t b1) {
    asm volatile(
        "mma.sync.aligned.m16n8k8.row.col.f32.tf32.tf32.f32 "
        "{%0,%1,%2,%3}, {%4,%5,%6,%7}, {%8,%9}, {%0,%1,%2,%3};\n"
        : "+f"(d[0]), "+f"(d[1]), "+f"(d[2]), "+f"(d[3])
        : "r"(a0), "r"(a1), "r"(a2), "r"(a3), "r"(b0), "r"(b1));
}

// ---------------------------------------------------------------------------
// Phase 1: one CTA per batch element b; produces g_ma[b][0..199]
// ---------------------------------------------------------------------------
__global__ __launch_bounds__(256) void phase1_kernel(
    const float* __restrict__ re,     // [B,U,D]
    const float* __restrict__ ret,    // [B,U,D]
    const float* __restrict__ mask,   // [B,T]
    const float* __restrict__ maskt,  // [B,T]
    const int*   __restrict__ alias,  // [B,T]
    const int*   __restrict__ aliast, // [B,T]
    const float* __restrict__ w1,     // [2D,2D]
    const float* __restrict__ w2,     // [2D,2D]
    const float* __restrict__ w3,     // [2D,2D]
    const float* __restrict__ v,      // [2D]
    const float* __restrict__ bias)   // [2D]
{
    extern __shared__ float sm1[];
    float* sh    = sm1;            // [40][200] gathered seq_htype
    float* cbuf  = sm1 + 8000;     // [40][200] coef partials
    float* lp    = sm1 + 16000;    // [200] (unused storage slot kept for clarity)
    float* coefs = sm1 + 16200;    // [40]
    float* svec  = sm1 + 16240;    // [200]
    float* lastv = sm1 + 16440;    // [200]
    __shared__ int sa[TT], sat[TT], slast[2];
    (void)lp;

    const int b = blockIdx.x;
    const int tid = threadIdx.x;

    if (tid < TT) {
        sa[tid]  = alias[b * TT + tid];
        sat[tid] = aliast[b * TT + tid];
    }
    if (tid == 0) {
        float s = 0.f, st = 0.f;
        for (int t = 0; t < TT; t++) { s += mask[b * TT + t]; st += maskt[b * TT + t]; }
        int rm  = (int)(s  + 0.5f); rm  = rm  < 1 ? 1 : (rm  > TT ? TT : rm);
        int rmt = (int)(st + 0.5f); rmt = rmt < 1 ? 1 : (rmt > TT ? TT : rmt);
        slast[0] = alias[b * TT + rm - 1];
        slast[1] = aliast[b * TT + rmt - 1];
    }
    __syncthreads();

    // gather seq_htype into smem: sh[t][k], k<100 from re, k>=100 from ret
    for (int idx = tid; idx < TT * D2; idx += 256) {
        int t = idx / D2, k = idx - t * D2;
        float val = (k < DD) ? re[(b * TT + sa[t]) * DD + k]
                             : ret[(b * TT + sat[t]) * DD + (k - DD)];
        sh[idx] = val;
    }
    if (tid < D2) {
        int k = tid;
        lastv[k] = (k < DD) ? re[(b * TT + slast[0]) * DD + k]
                            : ret[(b * TT + slast[1]) * DD + (k - DD)];
    }
    __syncthreads();

    const int j = tid;

    // last_proj[j] = lastvec @ w1[:, j]   (kept in register, only owner uses it)
    float lpj = 0.f;
    if (j < D2) {
        for (int k = 0; k < D2; k++) lpj += lastv[k] * w1[k * D2 + j];
    }

    // seq[t][j] = sh[t] @ w2[:, j] ; then m = sigmoid(lp + seq + b); cbuf = m*v[j]
    if (j < D2) {
        float acc[TT];
#pragma unroll
        for (int t = 0; t < TT; t++) acc[t] = 0.f;
        for (int k = 0; k < D2; k += 4) {
            float wa = w2[(k + 0) * D2 + j];
            float wb = w2[(k + 1) * D2 + j];
            float wc = w2[(k + 2) * D2 + j];
            float wd = w2[(k + 3) * D2 + j];
#pragma unroll
            for (int t = 0; t < TT; t++) {
                float4 s4 = *(const float4*)&sh[t * D2 + k];
                acc[t] += s4.x * wa + s4.y * wb + s4.z * wc + s4.w * wd;
            }
        }
        float vj = v[j], bj = bias[j];
#pragma unroll
        for (int t = 0; t < TT; t++) {
            float x = lpj + acc[t] + bj;
            float mval = 1.f / (1.f + expf(-x));
            cbuf[t * D2 + j] = mval * vj;
        }
    }
    __syncthreads();

    // coef[t] = (sum_j cbuf[t][j]) * mask[b][t]
    if (tid < TT) {
        float c = 0.f;
        for (int jj = 0; jj < D2; jj++) c += cbuf[tid * D2 + jj];
        coefs[tid] = c * mask[b * TT + tid];
    }
    __syncthreads();

    // s[k] = sum_t coef[t] * sh[t][k]
    if (tid < D2) {
        float s = 0.f;
#pragma unroll
        for (int t = 0; t < TT; t++) s += coefs[t] * sh[t * D2 + tid];
        svec[tid] = s;
    }
    __syncthreads();

    // ma[b][j] = s @ w3[:, j]   (w3 pulled outside the t-sum by linearity)
    if (j < D2) {
        float m = 0.f;
        for (int k = 0; k < D2; k++) m += svec[k] * w3[k * D2 + j];
        g_ma[b * D2 + j] = m;
    }
}

// ---------------------------------------------------------------------------
// Phase 2: logits[256][199999] = ma @ b_emb^T   (tf32 mma.sync, BM=BN=128)
// b_emb[n][k] = k<100 ? embedding[n+1][k] : embedding_type[csort[n+1]][k-100]
// K handled as two halves of 100, each zero-padded to 104 (13 k8-steps).
// ---------------------------------------------------------------------------
#define SM_STRIDE 108   // floats per smem row (conflict-free for frag loads)

__global__ __launch_bounds__(256) void phase2_kernel(
    const float* __restrict__ emb,    // [N_NODE, 100]
    const float* __restrict__ embt,   // [N_TYPE, 100]
    const int*   __restrict__ csort,  // [N_NODE]
    float* __restrict__ out)          // [256, 199999]
{
    extern __shared__ float sm2[];
    float* As = sm2;                      // [128][108]
    float* Bs = sm2 + 128 * SM_STRIDE;    // [128][108]
    int*   sct = (int*)(sm2 + 2 * 128 * SM_STRIDE);  // [128]

    const int tid  = threadIdx.x;
    const int n0   = blockIdx.x * 128;
    const int m0   = blockIdx.y * 128;
    const int lane = tid & 31;
    const int warp = tid >> 5;
    const int wm = warp >> 2;   // 0..1 -> 64 rows each
    const int wn = warp & 3;    // 0..3 -> 32 cols each

    // stage gathered type indices for this column tile
    for (int i = tid; i < 128; i += 256) {
        int n = n0 + i;
        sct[i] = (n < NOUT) ? csort[n + 1] : 0;
    }

    float acc[4][4][4];
#pragma unroll
    for (int mt = 0; mt < 4; mt++)
#pragma unroll
        for (int nt = 0; nt < 4; nt++)
#pragma unroll
            for (int r = 0; r < 4; r++) acc[mt][nt][r] = 0.f;

    for (int h = 0; h < 2; h++) {
        __syncthreads();  // smem reuse barrier (also publishes sct on h==0)

        // ---- load A half: g_ma[m0..m0+127][h*100 .. +99] -> tf32 ----
        for (int idx = tid; idx < 128 * 25; idx += 256) {
            int r = idx / 25, c = idx % 25;
            float4 a = *(const float4*)(g_ma + (m0 + r) * D2 + h * DD + c * 4);
            float4 w;
            w.x = tf32_of(a.x); w.y = tf32_of(a.y);
            w.z = tf32_of(a.z); w.w = tf32_of(a.w);
            *(float4*)(As + r * SM_STRIDE + c * 4) = w;
        }
        for (int i = tid; i < 128; i += 256)
            *(float4*)(As + i * SM_STRIDE + 100) = make_float4(0.f, 0.f, 0.f, 0.f);

        // ---- load B half: constructed b_embedding rows -> tf32 ----
        for (int idx = tid; idx < 128 * 25; idx += 256) {
            int r = idx / 25, c = idx % 25;
            int n = n0 + r;
            float4 w = make_float4(0.f, 0.f, 0.f, 0.f);
            if (n < NOUT) {
                const float* src = (h == 0)
                    ? (emb + (size_t)(n + 1) * DD)
                    : (embt + (size_t)sct[r] * DD);
                float4 a = *(const float4*)(src + c * 4);
                w.x = tf32_of(a.x); w.y = tf32_of(a.y);
                w.z = tf32_of(a.z); w.w = tf32_of(a.w);
            }
            *(float4*)(Bs + r * SM_STRIDE + c * 4) = w;
        }
        for (int i = tid; i < 128; i += 256)
            *(float4*)(Bs + i * SM_STRIDE + 100) = make_float4(0.f, 0.f, 0.f, 0.f);

        __syncthreads();

        const float* ab = As + (wm * 64 + (lane >> 2)) * SM_STRIDE + (lane & 3);
        const float* bb = Bs + (wn * 32 + (lane >> 2)) * SM_STRIDE + (lane & 3);

#pragma unroll
        for (int ks = 0; ks < 13; ks++) {
            const int k0 = ks * 8;
            uint32_t af[4][4], bf[4][2];
#pragma unroll
            for (int mt = 0; mt < 4; mt++) {
                const float* p = ab + mt * 16 * SM_STRIDE + k0;
                af[mt][0] = __float_as_uint(p[0]);
                af[mt][1] = __float_as_uint(p[8 * SM_STRIDE]);
                af[mt][2] = __float_as_uint(p[4]);
                af[mt][3] = __float_as_uint(p[8 * SM_STRIDE + 4]);
            }
#pragma unroll
            for (int nt = 0; nt < 4; nt++) {
                const float* p = bb + nt * 8 * SM_STRIDE + k0;
                bf[nt][0] = __float_as_uint(p[0]);
                bf[nt][1] = __float_as_uint(p[4]);
            }
#pragma unroll
            for (int mt = 0; mt < 4; mt++)
#pragma unroll
                for (int nt = 0; nt < 4; nt++)
                    mma_tf32(acc[mt][nt],
                             af[mt][0], af[mt][1], af[mt][2], af[mt][3],
                             bf[nt][0], bf[nt][1]);
        }
    }

    // ---- epilogue: C fragment layout m16n8 ----
#pragma unroll
    for (int mt = 0; mt < 4; mt++) {
        int r = m0 + wm * 64 + mt * 16 + (lane >> 2);
#pragma unroll
        for (int nt = 0; nt < 4; nt++) {
            int c = n0 + wn * 32 + nt * 8 + 2 * (lane & 3);
            if (c < NOUT) {
                out[(size_t)r * NOUT + c]       = acc[mt][nt][0];
                out[(size_t)(r + 8) * NOUT + c] = acc[mt][nt][2];
                if (c + 1 < NOUT) {
                    out[(size_t)r * NOUT + c + 1]       = acc[mt][nt][1];
                    out[(size_t)(r + 8) * NOUT + c + 1] = acc[mt][nt][3];
                }
            }
        }
    }
}

// ---------------------------------------------------------------------------
// launch
// ---------------------------------------------------------------------------
extern "C" void kernel_launch(void* const* d_in, const int* in_sizes, int n_in,
                              void* d_out, int out_size) {
    (void)in_sizes; (void)n_in; (void)out_size;
    const float* re     = (const float*)d_in[0];
    const float* ret    = (const float*)d_in[1];
    const float* mask   = (const float*)d_in[2];
    const float* maskt  = (const float*)d_in[3];
    const int*   alias  = (const int*)d_in[4];
    const int*   aliast = (const int*)d_in[5];
    const int*   csort  = (const int*)d_in[6];
    const float* emb    = (const float*)d_in[7];
    const float* embt   = (const float*)d_in[8];
    const float* w1     = (const float*)d_in[9];
    const float* w2     = (const float*)d_in[10];
    const float* w3     = (const float*)d_in[11];
    const float* v      = (const float*)d_in[12];
    const float* bias   = (const float*)d_in[13];
    float* out = (float*)d_out;

    const size_t sm1 = (size_t)16640 * sizeof(float);                 // 66,560 B
    const size_t sm2 = (size_t)(2 * 128 * SM_STRIDE) * sizeof(float)  // A+B tiles
                     + 128 * sizeof(int);                             // csort stage
    cudaFuncSetAttribute(phase1_kernel, cudaFuncAttributeMaxDynamicSharedMemorySize, (int)sm1);
    cudaFuncSetAttribute(phase2_kernel, cudaFuncAttributeMaxDynamicSharedMemorySize, (int)sm2);

    phase1_kernel<<<BB, 256, sm1>>>(re, ret, mask, maskt, alias, aliast,
                                    w1, w2, w3, v, bias);

    dim3 grid2((NOUT + 127) / 128, 2, 1);  // 1563 x 2
    phase2_kernel<<<grid2, 256, sm2>>>(emb, embt, csort, out);
}

// round 6
// speedup vs baseline: 1.4584x; 1.4584x over previous
#include <cuda_runtime.h>
#include <cstdint>
#include <math.h>

#define BB 256
#define TT 40
#define DD 100
#define D2 200
#define NNODE 200000
#define NOUT 199999   // N_NODE - 1

// scratch for ma [256][200] (tf32-rounded), device global (no allocs allowed)
__device__ float g_ma[BB * D2];

// ---------------------------------------------------------------------------
// helpers
// ---------------------------------------------------------------------------
__device__ __forceinline__ float tf32_of(float x) {
    uint32_t u;
    asm("cvt.rna.tf32.f32 %0, %1;" : "=r"(u) : "f"(x));
    return __uint_as_float(u);
}

__device__ __forceinline__ void mma_tf32(float d[4],
                                         uint32_t a0, uint32_t a1, uint32_t a2, uint32_t a3,
                                         uint32_t b0, uint32_t b1) {
    asm volatile(
        "mma.sync.aligned.m16n8k8.row.col.f32.tf32.tf32.f32 "
        "{%0,%1,%2,%3}, {%4,%5,%6,%7}, {%8,%9}, {%0,%1,%2,%3};\n"
        : "+f"(d[0]), "+f"(d[1]), "+f"(d[2]), "+f"(d[3])
        : "r"(a0), "r"(a1), "r"(a2), "r"(a3), "r"(b0), "r"(b1));
}

__device__ __forceinline__ void ldsm_x4(uint32_t& r0, uint32_t& r1,
                                        uint32_t& r2, uint32_t& r3, uint32_t addr) {
    asm volatile("ldmatrix.sync.aligned.m8n8.x4.shared.b16 {%0,%1,%2,%3}, [%4];"
                 : "=r"(r0), "=r"(r1), "=r"(r2), "=r"(r3) : "r"(addr));
}

__device__ __forceinline__ unsigned long long pack2(float lo, float hi) {
    unsigned long long r;
    asm("mov.b64 %0, {%1,%2};" : "=l"(r) : "f"(lo), "f"(hi));
    return r;
}
__device__ __forceinline__ void ffma2(unsigned long long& d,
                                      unsigned long long a, unsigned long long b) {
    asm("fma.rn.f32x2 %0, %1, %2, %0;" : "+l"(d) : "l"(a), "l"(b));
}
__device__ __forceinline__ float2 unpack2(unsigned long long v) {
    float2 f;
    asm("mov.b64 {%0,%1}, %2;" : "=f"(f.x), "=f"(f.y) : "l"(v));
    return f;
}

__device__ __forceinline__ void mbar_init(uint32_t mbar, uint32_t cnt) {
    asm volatile("mbarrier.init.shared.b64 [%0], %1;" :: "r"(mbar), "r"(cnt) : "memory");
}
__device__ __forceinline__ void mbar_expect_tx(uint32_t mbar, uint32_t tx) {
    asm volatile("mbarrier.arrive.expect_tx.shared.b64 _, [%0], %1;"
                 :: "r"(mbar), "r"(tx) : "memory");
}
__device__ __forceinline__ void mbar_wait(uint32_t mbar, uint32_t parity) {
    asm volatile(
        "{\n\t.reg .pred P;\n\t"
        "WL_%=:\n\t"
        "mbarrier.try_wait.parity.acquire.cta.shared::cta.b64 P, [%0], %1, 0x989680;\n\t"
        "@P bra WD_%=;\n\t"
        "bra WL_%=;\n\t"
        "WD_%=:\n\t}"
        :: "r"(mbar), "r"(parity) : "memory");
}
__device__ __forceinline__ void bulk_g2s(uint32_t dst, const void* src, uint32_t bytes,
                                         uint32_t mbar) {
    asm volatile(
        "cp.async.bulk.shared::cta.global.mbarrier::complete_tx::bytes [%0], [%1], %2, [%3];"
        :: "r"(dst), "l"(src), "r"(bytes), "r"(mbar) : "memory");
}

// ---------------------------------------------------------------------------
// Phase 1: one CTA per 2 batch elements; produces g_ma[b][0..199] (tf32-rounded)
// ---------------------------------------------------------------------------
__global__ __launch_bounds__(256) void phase1_kernel(
    const float* __restrict__ re,     // [B,U,D]
    const float* __restrict__ ret,    // [B,U,D]
    const float* __restrict__ mask,   // [B,T]
    const float* __restrict__ maskt,  // [B,T]
    const int*   __restrict__ alias,  // [B,T]
    const int*   __restrict__ aliast, // [B,T]
    const float* __restrict__ w1,     // [2D,2D]
    const float* __restrict__ w2,     // [2D,2D]
    const float* __restrict__ w3,     // [2D,2D]
    const float* __restrict__ v,      // [2D]
    const float* __restrict__ bias)   // [2D]
{
    extern __shared__ float sm1[];
    float* sh    = sm1;            // [40][200]
    float* cbuf  = sm1 + 8000;     // [40][200]
    float* coefs = sm1 + 16000;    // [40]
    float* svec  = sm1 + 16040;    // [200]
    float* lastv = sm1 + 16240;    // [200]
    __shared__ int sa[TT], sat[TT], slast[2];

    const int tid = threadIdx.x;
    const int j = tid;

    for (int bi = 0; bi < 2; bi++) {
        const int b = blockIdx.x * 2 + bi;

        if (tid < TT) {
            sa[tid]  = alias[b * TT + tid];
            sat[tid] = aliast[b * TT + tid];
        }
        if (tid == 0) {
            float s = 0.f, st = 0.f;
            for (int t = 0; t < TT; t++) { s += mask[b * TT + t]; st += maskt[b * TT + t]; }
            int rm  = (int)(s  + 0.5f); rm  = rm  < 1 ? 1 : (rm  > TT ? TT : rm);
            int rmt = (int)(st + 0.5f); rmt = rmt < 1 ? 1 : (rmt > TT ? TT : rmt);
            slast[0] = alias[b * TT + rm - 1];
            slast[1] = aliast[b * TT + rmt - 1];
        }
        __syncthreads();

        for (int idx = tid; idx < TT * D2; idx += 256) {
            int t = idx / D2, k = idx - t * D2;
            sh[idx] = (k < DD) ? re[(b * TT + sa[t]) * DD + k]
                               : ret[(b * TT + sat[t]) * DD + (k - DD)];
        }
        if (tid < D2) {
            lastv[tid] = (tid < DD) ? re[(b * TT + slast[0]) * DD + tid]
                                    : ret[(b * TT + slast[1]) * DD + (tid - DD)];
        }
        __syncthreads();

        float lpj = 0.f;
        if (j < D2) {
            for (int k = 0; k < D2; k++) lpj += lastv[k] * w1[k * D2 + j];
        }

        if (j < D2) {
            unsigned long long acc2[TT];
            const unsigned long long z = pack2(0.f, 0.f);
#pragma unroll
            for (int t = 0; t < TT; t++) acc2[t] = z;
            for (int k = 0; k < D2; k += 4) {
                unsigned long long w01 = pack2(w2[(k + 0) * D2 + j], w2[(k + 1) * D2 + j]);
                unsigned long long w23 = pack2(w2[(k + 2) * D2 + j], w2[(k + 3) * D2 + j]);
#pragma unroll
                for (int t = 0; t < TT; t++) {
                    ulonglong2 s2 = *(const ulonglong2*)&sh[t * D2 + k];
                    ffma2(acc2[t], s2.x, w01);
                    ffma2(acc2[t], s2.y, w23);
                }
            }
            float vj = v[j], bj = bias[j];
#pragma unroll
            for (int t = 0; t < TT; t++) {
                float2 u = unpack2(acc2[t]);
                float x = lpj + u.x + u.y + bj;
                float mval = 1.f / (1.f + expf(-x));
                cbuf[t * D2 + j] = mval * vj;
            }
        }
        __syncthreads();

        if (tid < TT) {
            float c = 0.f;
            for (int jj = 0; jj < D2; jj++) c += cbuf[tid * D2 + jj];
            coefs[tid] = c * mask[b * TT + tid];
        }
        __syncthreads();

        if (tid < D2) {
            float s = 0.f;
#pragma unroll
            for (int t = 0; t < TT; t++) s += coefs[t] * sh[t * D2 + tid];
            svec[tid] = s;
        }
        __syncthreads();

        if (j < D2) {
            float m = 0.f;
            for (int k = 0; k < D2; k++) m += svec[k] * w3[k * D2 + j];
            g_ma[b * D2 + j] = tf32_of(m);   // pre-round A operand for phase 2
        }
        __syncthreads();
    }
}

// ---------------------------------------------------------------------------
// Phase 2: logits[256][199999] = ma @ b_emb^T
// tf32 mma.sync, BM=BN=128, K split into 5 chunks of 40.
// cp.async.bulk double-buffered staging (160 B per row per chunk),
// ldmatrix.x4 fragments, smem-staged coalesced epilogue.
// Grid = (2 m-tiles [fast], 1563 n-tiles) for L2 reuse of emb.
// ---------------------------------------------------------------------------
#define KCH   40            // K per chunk (= 5 ks-steps, no padding)
#define NCH   5
#define SSTR  44            // smem row stride in floats (12-bank offset: conflict-free)
#define ROWB  (SSTR * 4)    // 176 bytes per row
#define MATB  (128 * ROWB)  // 22528 bytes per matrix
#define BUFB  (2 * MATB)    // 45056 bytes per (A,B) stage
#define MBAR_OFF (2 * BUFB) // 90112
#define SMEM2 (MBAR_OFF + 16)
#define TXB   (2u * 128u * 160u)  // 40960 bytes expected per chunk
#define CSTR  132           // epilogue smem stride (4-bank offset: conflict-free)

__global__ __launch_bounds__(256, 2) void phase2_kernel(
    const float* __restrict__ emb,    // [N_NODE, 100]
    const float* __restrict__ embt,   // [N_TYPE, 100]
    const int*   __restrict__ csort,  // [N_NODE]
    float* __restrict__ out)          // [256, 199999]
{
    extern __shared__ float sm2[];
    const uint32_t sb = (uint32_t)__cvta_generic_to_shared(sm2);

    const int tid  = threadIdx.x;
    const int m0   = blockIdx.x * 128;
    const int n0   = blockIdx.y * 128;
    const int lane = tid & 31;
    const int warp = tid >> 5;
    const int wm = warp >> 2;   // 0..1 -> 64 rows
    const int wn = warp & 3;    // 0..3 -> 32 cols

    const uint32_t mbar0 = sb + MBAR_OFF;
    const uint32_t mbar1 = sb + MBAR_OFF + 8;

    if (tid == 0) { mbar_init(mbar0, 1); mbar_init(mbar1, 1); }
    __syncthreads();

    // precompute this thread's staging source/destination
    const int srow = tid & 127;               // row handled by this thread
    const bool isA = (tid < 128);
    const float* arow = g_ma + (size_t)(m0 + srow) * D2;
    int nn = n0 + srow + 1; if (nn > NNODE - 1) nn = NNODE - 1;
    const float* brow  = emb + (size_t)nn * DD;
    const float* btrow = isA ? nullptr : (embt + (size_t)csort[nn] * DD);
    const uint32_t dst0 = sb + (isA ? 0u : (uint32_t)MATB) + (uint32_t)srow * ROWB;

    // fragment base addresses (byte, shared space), at chunk-k0 = 0, buffer 0
    uint32_t baseA[4], baseB[2];
#pragma unroll
    for (int mt = 0; mt < 4; mt++) {
        int row = wm * 64 + mt * 16 + (lane & 15);
        int col = (lane >> 4) << 2;
        baseA[mt] = sb + (uint32_t)(row * SSTR + col) * 4u;
    }
#pragma unroll
    for (int p = 0; p < 2; p++) {
        int row = wn * 32 + p * 16 + (lane & 7) + ((lane >> 4) & 1) * 8;
        int col = ((lane >> 3) & 1) << 2;
        baseB[p] = sb + (uint32_t)MATB + (uint32_t)(row * SSTR + col) * 4u;
    }

    float acc[4][4][4];
#pragma unroll
    for (int mt = 0; mt < 4; mt++)
#pragma unroll
        for (int nt = 0; nt < 4; nt++)
#pragma unroll
            for (int r = 0; r < 4; r++) acc[mt][nt][r] = 0.f;

    // ---- issue chunk (all 256 threads: one row each; tid0 posts expect_tx) ----
    auto issue_chunk = [&](int ch) {
        const uint32_t s = (uint32_t)(ch & 1);
        const uint32_t mb = (ch & 1) ? mbar1 : mbar0;
        if (tid == 0) mbar_expect_tx(mb, TXB);
        const uint32_t dst = dst0 + s * BUFB;
        const int k0 = ch * KCH;
        if (isA) {
            bulk_g2s(dst, arow + k0, 160, mb);
        } else {
            if (k0 + KCH <= DD) {
                bulk_g2s(dst, brow + k0, 160, mb);
            } else if (k0 >= DD) {
                bulk_g2s(dst, btrow + (k0 - DD), 160, mb);
            } else {  // mixed chunk: 80 B from emb + 80 B from embt
                bulk_g2s(dst,      brow + k0, 80, mb);
                bulk_g2s(dst + 80, btrow,     80, mb);
            }
        }
    };

    issue_chunk(0);
    issue_chunk(1);

    for (int c = 0; c < NCH; c++) {
        const uint32_t mb = (c & 1) ? mbar1 : mbar0;
        mbar_wait(mb, (uint32_t)((c >> 1) & 1));

        const uint32_t sOff = (uint32_t)(c & 1) * BUFB;
#pragma unroll
        for (int ks = 0; ks < 5; ks++) {
            const uint32_t kadd = sOff + (uint32_t)ks * 32u;
            uint32_t af[4][4], bf[4][2];
#pragma unroll
            for (int mt = 0; mt < 4; mt++)
                ldsm_x4(af[mt][0], af[mt][1], af[mt][2], af[mt][3], baseA[mt] + kadd);
#pragma unroll
            for (int p = 0; p < 2; p++) {
                uint32_t r0, r1, r2, r3;
                ldsm_x4(r0, r1, r2, r3, baseB[p] + kadd);
                bf[2 * p][0] = r0; bf[2 * p][1] = r1;
                bf[2 * p + 1][0] = r2; bf[2 * p + 1][1] = r3;
            }
#pragma unroll
            for (int mt = 0; mt < 4; mt++)
#pragma unroll
                for (int nt = 0; nt < 4; nt++)
                    mma_tf32(acc[mt][nt],
                             af[mt][0], af[mt][1], af[mt][2], af[mt][3],
                             bf[nt][0], bf[nt][1]);
        }
        __syncthreads();           // everyone done reading this buffer
        if (c + 2 < NCH) issue_chunk(c + 2);
    }

    // ---- epilogue: stage through smem, store coalesced ----
    float* Cs = sm2;  // 128 x CSTR floats = 67,584 B (overlaps stage buffers)
#pragma unroll
    for (int mt = 0; mt < 4; mt++) {
        int r1 = wm * 64 + mt * 16 + (lane >> 2);
#pragma unroll
        for (int nt = 0; nt < 4; nt++) {
            int cc = wn * 32 + nt * 8 + 2 * (lane & 3);
            Cs[r1 * CSTR + cc]           = acc[mt][nt][0];
            Cs[r1 * CSTR + cc + 1]       = acc[mt][nt][1];
            Cs[(r1 + 8) * CSTR + cc]     = acc[mt][nt][2];
            Cs[(r1 + 8) * CSTR + cc + 1] = acc[mt][nt][3];
        }
    }
    __syncthreads();

    // 128x128 floats, warp-contiguous scalar stores (coalesced 128B/warp)
    for (int idx = tid; idx < 128 * 128; idx += 256) {
        int r = idx >> 7, cc = idx & 127;
        int n = n0 + cc;
        if (n < NOUT)
            out[(size_t)(m0 + r) * NOUT + n] = Cs[r * CSTR + cc];
    }
}

// ---------------------------------------------------------------------------
// launch
// ---------------------------------------------------------------------------
extern "C" void kernel_launch(void* const* d_in, const int* in_sizes, int n_in,
                              void* d_out, int out_size) {
    (void)in_sizes; (void)n_in; (void)out_size;
    const float* re     = (const float*)d_in[0];
    const float* ret    = (const float*)d_in[1];
    const float* mask   = (const float*)d_in[2];
    const float* maskt  = (const float*)d_in[3];
    const int*   alias  = (const int*)d_in[4];
    const int*   aliast = (const int*)d_in[5];
    const int*   csort  = (const int*)d_in[6];
    const float* emb    = (const float*)d_in[7];
    const float* embt   = (const float*)d_in[8];
    const float* w1     = (const float*)d_in[9];
    const float* w2     = (const float*)d_in[10];
    const float* w3     = (const float*)d_in[11];
    const float* v      = (const float*)d_in[12];
    const float* bias   = (const float*)d_in[13];
    float* out = (float*)d_out;

    const size_t sm1 = (size_t)16440 * sizeof(float);   // 65,760 B
    const size_t sm2 = (size_t)SMEM2;                   // 90,128 B
    cudaFuncSetAttribute(phase1_kernel, cudaFuncAttributeMaxDynamicSharedMemorySize, (int)sm1);
    cudaFuncSetAttribute(phase2_kernel, cudaFuncAttributeMaxDynamicSharedMemorySize, (int)sm2);

    phase1_kernel<<<BB / 2, 256, sm1>>>(re, ret, mask, maskt, alias, aliast,
                                        w1, w2, w3, v, bias);

    dim3 grid2(2, (NOUT + 127) / 128, 1);  // m-fast x 1563 n-tiles
    phase2_kernel<<<grid2, 256, sm2>>>(emb, embt, csort, out);
}